// round 2
// baseline (speedup 1.0000x reference)
#include <cuda_runtime.h>
#include <cuda_bf16.h>

// Problem constants
#define C_IN   256
#define C_OUT  256
#define HW     56
#define HWSQ   (HW * HW)          // 3136
#define KTAPS  9
#define KELEM  (C_IN * KTAPS)     // 2304 per output channel

// Scratch: quantized+scaled weights, [oc][ic][kh*3+kw], fp32.
__device__ float g_wq[(size_t)C_OUT * KELEM];

// ---------------------------------------------------------------------------
// Kernel A: ternary quantization. One block per output channel.
// delta = 0.7 * mean(|w|); ternary = sign-threshold; alpha = mean(|w| over
// nonzero taps); writes alpha*ternary.
// ---------------------------------------------------------------------------
__global__ void quant_kernel(const float* __restrict__ w) {
    const int oc  = blockIdx.x;
    const int tid = threadIdx.x;
    const float* wo = w + (size_t)oc * KELEM;
    __shared__ float red[256];

    // Pass 1: sum |w|
    float s = 0.f;
    for (int i = tid; i < KELEM; i += 256) s += fabsf(wo[i]);
    red[tid] = s;
    __syncthreads();
    #pragma unroll
    for (int st = 128; st > 0; st >>= 1) {
        if (tid < st) red[tid] += red[tid + st];
        __syncthreads();
    }
    const float delta = 0.7f * red[0] / (float)KELEM;
    __syncthreads();

    // Pass 2: masked sum + count
    float ms = 0.f, cnt = 0.f;
    for (int i = tid; i < KELEM; i += 256) {
        float a = fabsf(wo[i]);
        if (a > delta) { ms += a; cnt += 1.f; }
    }
    red[tid] = ms;
    __syncthreads();
    #pragma unroll
    for (int st = 128; st > 0; st >>= 1) {
        if (tid < st) red[tid] += red[tid + st];
        __syncthreads();
    }
    const float mtot = red[0];
    __syncthreads();
    red[tid] = cnt;
    __syncthreads();
    #pragma unroll
    for (int st = 128; st > 0; st >>= 1) {
        if (tid < st) red[tid] += red[tid + st];
        __syncthreads();
    }
    const float ctot = red[0];
    const float alpha = mtot / fmaxf(ctot, 1.f);

    // Pass 3: write scaled ternary weights
    float* dst = g_wq + (size_t)oc * KELEM;
    for (int i = tid; i < KELEM; i += 256) {
        float v = wo[i];
        dst[i] = (v > delta) ? alpha : ((v < -delta) ? -alpha : 0.f);
    }
}

// ---------------------------------------------------------------------------
// Kernel B: direct 3x3 conv, stride 1, pad 1, fp32.
// Tile per CTA: 64 output channels x (8 x 8) output pixels, one n.
// IC chunked by 8. Thread register tile: 4 oc x 4 contiguous ow pixels.
// Thread map (256 threads): pxg = tid & 15  -> (row r = pxg>>1, colgroup cg = pxg&1)
//                           ocg = tid >> 4  -> local oc base = ocg*4
// ---------------------------------------------------------------------------
#define ICC     8
#define TOC     64
#define TILE_H  8
#define TILE_W  8

__global__ __launch_bounds__(256) void conv_kernel(
    const float* __restrict__ x, float* __restrict__ out)
{
    __shared__ float sIn[ICC][10][12];       // rows 10, cols 0..9 used
    __shared__ float sW[TOC][ICC][12];       // 9 taps used, padded to 12 for f4 align

    const int tid = threadIdx.x;
    const int pxg = tid & 15;
    const int ocg = tid >> 4;
    const int r   = pxg >> 1;        // 0..7 tile row
    const int cg  = pxg & 1;         // 0..1 -> ow base 4*cg
    const int ocl = ocg * 4;         // local oc base 0..60

    const int n    = blockIdx.z;
    const int oc0  = blockIdx.y * TOC;
    const int tile = blockIdx.x;     // 0..48
    const int oh0  = (tile / 7) * TILE_H;
    const int ow0  = (tile % 7) * TILE_W;

    const float* xn = x + (size_t)n * C_IN * HWSQ;

    float acc[4][4];
    #pragma unroll
    for (int o = 0; o < 4; o++)
        #pragma unroll
        for (int p = 0; p < 4; p++) acc[o][p] = 0.f;

    for (int ic0 = 0; ic0 < C_IN; ic0 += ICC) {
        __syncthreads();
        // ---- load input halo tile: ICC x 10 x 10 ----
        for (int idx = tid; idx < ICC * 100; idx += 256) {
            int ic = idx / 100;
            int rem = idx - ic * 100;
            int rr = rem / 10;
            int cc = rem - rr * 10;
            int ih = oh0 - 1 + rr;
            int iw = ow0 - 1 + cc;
            float v = 0.f;
            if ((unsigned)ih < (unsigned)HW && (unsigned)iw < (unsigned)HW)
                v = xn[(size_t)(ic0 + ic) * HWSQ + ih * HW + iw];
            sIn[ic][rr][cc] = v;
        }
        // ---- load weight tile: TOC x ICC x 9 ----
        for (int idx = tid; idx < TOC * ICC * KTAPS; idx += 256) {
            int oc = idx / (ICC * KTAPS);
            int rem = idx - oc * (ICC * KTAPS);
            int ic = rem / KTAPS;
            int k  = rem - ic * KTAPS;
            sW[oc][ic][k] = g_wq[(size_t)(oc0 + oc) * KELEM + (ic0 + ic) * KTAPS + k];
        }
        __syncthreads();

        // ---- compute ----
        #pragma unroll
        for (int ic = 0; ic < ICC; ic++) {
            float xin[3][6];
            #pragma unroll
            for (int kh = 0; kh < 3; kh++) {
                const float* row = &sIn[ic][r + kh][4 * cg];
                float4 a = *(const float4*)row;
                float2 b = *(const float2*)(row + 4);
                xin[kh][0] = a.x; xin[kh][1] = a.y; xin[kh][2] = a.z; xin[kh][3] = a.w;
                xin[kh][4] = b.x; xin[kh][5] = b.y;
            }
            #pragma unroll
            for (int o = 0; o < 4; o++) {
                const float* wp = sW[ocl + o][ic];
                float4 w0 = *(const float4*)wp;
                float4 w1 = *(const float4*)(wp + 4);
                float  w8 = wp[8];
                float wv[9];
                wv[0] = w0.x; wv[1] = w0.y; wv[2] = w0.z; wv[3] = w0.w;
                wv[4] = w1.x; wv[5] = w1.y; wv[6] = w1.z; wv[7] = w1.w;
                wv[8] = w8;
                #pragma unroll
                for (int kh = 0; kh < 3; kh++) {
                    #pragma unroll
                    for (int kw = 0; kw < 3; kw++) {
                        float wr = wv[kh * 3 + kw];
                        #pragma unroll
                        for (int p = 0; p < 4; p++)
                            acc[o][p] += wr * xin[kh][kw + p];
                    }
                }
            }
        }
    }

    // ---- epilogue ----
    const int oh = oh0 + r;
    const int owb = ow0 + 4 * cg;
    #pragma unroll
    for (int o = 0; o < 4; o++) {
        const int oc = oc0 + ocl + o;
        float* dst = out + ((size_t)(n * C_OUT + oc)) * HWSQ + oh * HW + owb;
        #pragma unroll
        for (int p = 0; p < 4; p++) dst[p] = acc[o][p];
    }
}

// ---------------------------------------------------------------------------
extern "C" void kernel_launch(void* const* d_in, const int* in_sizes, int n_in,
                              void* d_out, int out_size) {
    const float* x = (const float*)d_in[0];
    const float* w = (const float*)d_in[1];
    float* out = (float*)d_out;

    quant_kernel<<<C_OUT, 256>>>(w);

    dim3 grid(49, C_OUT / TOC, 32);   // spatial tiles, oc tiles, batch
    conv_kernel<<<grid, 256>>>(x, out);

    (void)in_sizes; (void)n_in; (void)out_size;
}

// round 5
// speedup vs baseline: 4.9766x; 4.9766x over previous
#include <cuda_runtime.h>
#include <cuda_bf16.h>
#include <cstdint>

#define HW 56
#define HWSQ 3136
#define KTAPS 9
#define KELEM 2304

// Ternary weights as bf16 {-1,0,+1}: layout [chunk 8][tap 9][oc 256][k 32]
__device__ __nv_bfloat16 g_wB[8 * 9 * 256 * 32];
__device__ float g_alpha[256];

static __device__ __forceinline__ uint32_t smem_u32(const void* p) {
    uint32_t a;
    asm("{ .reg .u64 t; cvta.to.shared.u64 t, %1; cvt.u32.u64 %0, t; }" : "=r"(a) : "l"(p));
    return a;
}

// ---------------- quantization ----------------
__global__ void quant_kernel(const float* __restrict__ w) {
    const int oc = blockIdx.x, tid = threadIdx.x;
    const float* wo = w + (size_t)oc * KELEM;
    __shared__ float red[256];
    float s = 0.f;
    for (int i = tid; i < KELEM; i += 256) s += fabsf(wo[i]);
    red[tid] = s; __syncthreads();
    #pragma unroll
    for (int st = 128; st > 0; st >>= 1) { if (tid < st) red[tid] += red[tid + st]; __syncthreads(); }
    const float delta = 0.7f * red[0] / (float)KELEM;
    __syncthreads();
    float ms = 0.f, cnt = 0.f;
    for (int i = tid; i < KELEM; i += 256) {
        float a = fabsf(wo[i]);
        if (a > delta) { ms += a; cnt += 1.f; }
    }
    red[tid] = ms; __syncthreads();
    #pragma unroll
    for (int st = 128; st > 0; st >>= 1) { if (tid < st) red[tid] += red[tid + st]; __syncthreads(); }
    const float mtot = red[0];
    __syncthreads();
    red[tid] = cnt; __syncthreads();
    #pragma unroll
    for (int st = 128; st > 0; st >>= 1) { if (tid < st) red[tid] += red[tid + st]; __syncthreads(); }
    const float alpha = mtot / fmaxf(red[0], 1.f);
    if (tid == 0) g_alpha[oc] = alpha;

    for (int i = tid; i < KELEM; i += 256) {
        const int ic = i / KTAPS, tap = i - ic * KTAPS;
        const float v = wo[i];
        const float t = (v > delta) ? 1.f : ((v < -delta) ? -1.f : 0.f);
        g_wB[(((size_t)(ic >> 5) * 9 + tap) * 256 + oc) * 32 + (ic & 31)] = __float2bfloat16(t);
    }
}

// ---------------- conv via mma.sync (bf16, hi/lo split) ----------------
// SMEM layout (dynamic):
//  XH: [4 rows][66 cols][40 k pad] bf16 = 21120 B
//  XL: same @21120
//  A:  2 bufs x [128 oc][40 k pad] bf16 = 2 x 10240 @42240
#define SM_XH 0
#define SM_XL 21120
#define SM_A  42240
#define SM_TOTAL 62720
#define XROWB 80          // (40 bf16) padded row stride, bytes

__global__ __launch_bounds__(256, 2) void conv_mma(
    const float* __restrict__ x, float* __restrict__ out)
{
    extern __shared__ char smem[];
    const uint32_t sb = smem_u32(smem);
    const int tid = threadIdx.x, wid = tid >> 5, lane = tid & 31;
    const int oct = blockIdx.x;          // 0..1 (oc half)
    const int rowbase = blockIdx.y * 2;  // 0..54 step 2
    const int nimg = blockIdx.z;

    const int wm = wid & 1;              // oc 64-half within CTA tile
    const int q  = wid >> 1;             // pixel quarter
    const int orow = q >> 1;             // 0..1
    const int c0 = (q & 1) * 32;         // col base

    const float* xb = x + (size_t)nimg * 256 * HWSQ;

    float acc[4][4][4];
    #pragma unroll
    for (int a = 0; a < 4; a++)
        #pragma unroll
        for (int b = 0; b < 4; b++)
            #pragma unroll
            for (int e = 0; e < 4; e++) acc[a][b][e] = 0.f;

    // issue A load for iter 0
    {
        const __nv_bfloat16* src = g_wB + ((size_t)0 * 256 + oct * 128) * 32;
        #pragma unroll
        for (int it = 0; it < 2; it++) {
            const int idx = tid + it * 256;          // 0..511
            const int r = idx >> 2, seg = idx & 3;
            const uint32_t dst = sb + SM_A + (uint32_t)(r * XROWB + seg * 16);
            asm volatile("cp.async.cg.shared.global [%0], [%1], 16;"
                         :: "r"(dst), "l"(src + r * 32 + seg * 8) : "memory");
        }
        asm volatile("cp.async.commit_group;" ::: "memory");
    }

    const int j = tid & 63;          // col index 0..63
    const int high = tid >> 6;       // 0..3

    for (int i = 0; i < 72; i++) {
        const int c = i / 9, t = i - c * 9;
        const int buf = i & 1;
        const int kh = t / 3, kw = t - kh * 3;

        if (t == 0) {
            // build x tiles (hi+lo) for chunk c: rows 0..3 (ih=rowbase-1+row),
            // cols 0..65 (iw=col-1), k 0..31 (ic = c*32+k)
            #pragma unroll 4
            for (int idx = high; idx < 128; idx += 4) {
                const int row = idx & 3, k = idx >> 2;
                const int ih = rowbase - 1 + row, iw = j - 1;
                float v = 0.f;
                if ((unsigned)ih < (unsigned)HW && (unsigned)iw < (unsigned)HW)
                    v = xb[(size_t)(c * 32 + k) * HWSQ + ih * HW + iw];
                const __nv_bfloat16 h = __float2bfloat16(v);
                const __nv_bfloat16 l = __float2bfloat16(v - __bfloat162float(h));
                const uint32_t off = (uint32_t)((row * 66 + j) * 40 + k) * 2;
                *(__nv_bfloat16*)(smem + SM_XH + off) = h;
                *(__nv_bfloat16*)(smem + SM_XL + off) = l;
            }
            {   // tail cols 64,65
                const int k = tid & 31, row = (tid >> 5) & 3, col = 64 + (tid >> 7);
                const int ih = rowbase - 1 + row, iw = col - 1;
                float v = 0.f;
                if ((unsigned)ih < (unsigned)HW && (unsigned)iw < (unsigned)HW)
                    v = xb[(size_t)(c * 32 + k) * HWSQ + ih * HW + iw];
                const __nv_bfloat16 h = __float2bfloat16(v);
                const __nv_bfloat16 l = __float2bfloat16(v - __bfloat162float(h));
                const uint32_t off = (uint32_t)((row * 66 + col) * 40 + k) * 2;
                *(__nv_bfloat16*)(smem + SM_XH + off) = h;
                *(__nv_bfloat16*)(smem + SM_XL + off) = l;
            }
        }

        asm volatile("cp.async.wait_group 0;" ::: "memory");
        __syncthreads();

        // prefetch next A
        if (i + 1 < 72) {
            const int c2 = (i + 1) / 9, t2 = (i + 1) - c2 * 9;
            const __nv_bfloat16* src = g_wB + (((size_t)c2 * 9 + t2) * 256 + oct * 128) * 32;
            const uint32_t abase = sb + SM_A + (uint32_t)((buf ^ 1) * 10240);
            #pragma unroll
            for (int it = 0; it < 2; it++) {
                const int idx = tid + it * 256;
                const int r = idx >> 2, seg = idx & 3;
                asm volatile("cp.async.cg.shared.global [%0], [%1], 16;"
                             :: "r"(abase + (uint32_t)(r * XROWB + seg * 16)),
                                "l"(src + r * 32 + seg * 8) : "memory");
            }
            asm volatile("cp.async.commit_group;" ::: "memory");
        }

        // ---- compute this (chunk, tap) ----
        const uint32_t aB = sb + SM_A + (uint32_t)(buf * 10240)
                          + (uint32_t)((wm * 64 + (lane & 15)) * XROWB + ((lane >> 4) << 4));
        const int pxo = (lane & 7) + ((lane & 16) ? 8 : 0);
        const uint32_t kbo = (lane & 8) ? 16u : 0u;
        const uint32_t xoff = (uint32_t)(((orow + kh) * 66 + c0 + kw + pxo) * XROWB) + kbo;
        const uint32_t bH = sb + SM_XH + xoff;
        const uint32_t bL = sb + SM_XL + xoff;

        #pragma unroll
        for (int ks = 0; ks < 2; ks++) {
            const uint32_t ko = (uint32_t)(ks * 32);
            uint32_t bh[8], bl[8];
            asm volatile("ldmatrix.sync.aligned.m8n8.x4.shared.b16 {%0,%1,%2,%3}, [%4];"
                : "=r"(bh[0]),"=r"(bh[1]),"=r"(bh[2]),"=r"(bh[3]) : "r"(bH + ko));
            asm volatile("ldmatrix.sync.aligned.m8n8.x4.shared.b16 {%0,%1,%2,%3}, [%4];"
                : "=r"(bh[4]),"=r"(bh[5]),"=r"(bh[6]),"=r"(bh[7]) : "r"(bH + ko + 16 * XROWB));
            asm volatile("ldmatrix.sync.aligned.m8n8.x4.shared.b16 {%0,%1,%2,%3}, [%4];"
                : "=r"(bl[0]),"=r"(bl[1]),"=r"(bl[2]),"=r"(bl[3]) : "r"(bL + ko));
            asm volatile("ldmatrix.sync.aligned.m8n8.x4.shared.b16 {%0,%1,%2,%3}, [%4];"
                : "=r"(bl[4]),"=r"(bl[5]),"=r"(bl[6]),"=r"(bl[7]) : "r"(bL + ko + 16 * XROWB));
            #pragma unroll
            for (int mf = 0; mf < 4; mf++) {
                uint32_t a0, a1, a2, a3;
                asm volatile("ldmatrix.sync.aligned.m8n8.x4.shared.b16 {%0,%1,%2,%3}, [%4];"
                    : "=r"(a0),"=r"(a1),"=r"(a2),"=r"(a3)
                    : "r"(aB + (uint32_t)(mf * 16 * XROWB) + ko));
                #pragma unroll
                for (int nf = 0; nf < 4; nf++) {
                    asm volatile("mma.sync.aligned.m16n8k16.row.col.f32.bf16.bf16.f32 "
                        "{%0,%1,%2,%3}, {%4,%5,%6,%7}, {%8,%9}, {%0,%1,%2,%3};"
                        : "+f"(acc[mf][nf][0]),"+f"(acc[mf][nf][1]),
                          "+f"(acc[mf][nf][2]),"+f"(acc[mf][nf][3])
                        : "r"(a0),"r"(a1),"r"(a2),"r"(a3), "r"(bh[nf*2]),"r"(bh[nf*2+1]));
                }
                #pragma unroll
                for (int nf = 0; nf < 4; nf++) {
                    asm volatile("mma.sync.aligned.m16n8k16.row.col.f32.bf16.bf16.f32 "
                        "{%0,%1,%2,%3}, {%4,%5,%6,%7}, {%8,%9}, {%0,%1,%2,%3};"
                        : "+f"(acc[mf][nf][0]),"+f"(acc[mf][nf][1]),
                          "+f"(acc[mf][nf][2]),"+f"(acc[mf][nf][3])
                        : "r"(a0),"r"(a1),"r"(a2),"r"(a3), "r"(bl[nf*2]),"r"(bl[nf*2+1]));
                }
            }
        }
        __syncthreads();
    }

    // ---- epilogue: scale by alpha, direct float2 stores ----
    const int oh = rowbase + orow;
    const int r = lane >> 2, cc = lane & 3;
    #pragma unroll
    for (int mf = 0; mf < 4; mf++) {
        const int oc = oct * 128 + wm * 64 + mf * 16 + r;
        const float al0 = g_alpha[oc];
        const float al1 = g_alpha[oc + 8];
        #pragma unroll
        for (int nf = 0; nf < 4; nf++) {
            const int ow = c0 + nf * 8 + cc * 2;
            if (ow < 56) {
                float* d0 = out + ((size_t)(nimg * 256 + oc)) * HWSQ + oh * HW + ow;
                float* d1 = d0 + (size_t)8 * HWSQ;
                *(float2*)d0 = make_float2(acc[mf][nf][0] * al0, acc[mf][nf][1] * al0);
                *(float2*)d1 = make_float2(acc[mf][nf][2] * al1, acc[mf][nf][3] * al1);
            }
        }
    }
}

extern "C" void kernel_launch(void* const* d_in, const int* in_sizes, int n_in,
                              void* d_out, int out_size) {
    const float* x = (const float*)d_in[0];
    const float* w = (const float*)d_in[1];
    float* out = (float*)d_out;

    quant_kernel<<<256, 256>>>(w);

    cudaFuncSetAttribute(conv_mma, cudaFuncAttributeMaxDynamicSharedMemorySize, SM_TOTAL);
    dim3 grid(2, 28, 32);
    conv_mma<<<grid, 256, SM_TOTAL>>>(x, out);

    (void)in_sizes; (void)n_in; (void)out_size;
}

// round 6
// speedup vs baseline: 6.0343x; 1.2126x over previous
#include <cuda_runtime.h>
#include <cuda_fp16.h>
#include <cstdint>

#define HW 56
#define HWSQ 3136
#define KTAPS 9
#define KELEM 2304

// Ternary weights as fp16 {-1,0,+1}: layout [chunk 8][tap 9][oc 256][k 32]
__device__ __half g_wB[8 * 9 * 256 * 32];
__device__ float g_alpha[256];

static __device__ __forceinline__ uint32_t smem_u32(const void* p) {
    uint32_t a;
    asm("{ .reg .u64 t; cvta.to.shared.u64 t, %1; cvt.u32.u64 %0, t; }" : "=r"(a) : "l"(p));
    return a;
}

// ---------------- quantization ----------------
__global__ void quant_kernel(const float* __restrict__ w) {
    const int oc = blockIdx.x, tid = threadIdx.x;
    const float* wo = w + (size_t)oc * KELEM;
    __shared__ float red[256];
    float s = 0.f;
    for (int i = tid; i < KELEM; i += 256) s += fabsf(wo[i]);
    red[tid] = s; __syncthreads();
    #pragma unroll
    for (int st = 128; st > 0; st >>= 1) { if (tid < st) red[tid] += red[tid + st]; __syncthreads(); }
    const float delta = 0.7f * red[0] / (float)KELEM;
    __syncthreads();
    float ms = 0.f, cnt = 0.f;
    for (int i = tid; i < KELEM; i += 256) {
        float a = fabsf(wo[i]);
        if (a > delta) { ms += a; cnt += 1.f; }
    }
    red[tid] = ms; __syncthreads();
    #pragma unroll
    for (int st = 128; st > 0; st >>= 1) { if (tid < st) red[tid] += red[tid + st]; __syncthreads(); }
    const float mtot = red[0];
    __syncthreads();
    red[tid] = cnt; __syncthreads();
    #pragma unroll
    for (int st = 128; st > 0; st >>= 1) { if (tid < st) red[tid] += red[tid + st]; __syncthreads(); }
    const float alpha = mtot / fmaxf(red[0], 1.f);
    if (tid == 0) g_alpha[oc] = alpha;

    for (int i = tid; i < KELEM; i += 256) {
        const int ic = i / KTAPS, tap = i - ic * KTAPS;
        const float v = wo[i];
        const float t = (v > delta) ? 1.f : ((v < -delta) ? -1.f : 0.f);
        g_wB[(((size_t)(ic >> 5) * 9 + tap) * 256 + oc) * 32 + (ic & 31)] = __float2half_rn(t);
    }
}

// ---------------- conv via mma.sync (fp16 single pass) ----------------
// SMEM layout (dynamic):
//  XH: [4 rows][66 cols][40 k pad] fp16 = 21120 B
//  A:  2 bufs x [128 oc][40 k pad] fp16 = 2 x 10240 @21120
#define SM_XH 0
#define SM_A  21120
#define SM_TOTAL 41600
#define XROWB 80          // (40 halves) padded row stride, bytes

__global__ __launch_bounds__(256, 3) void conv_mma(
    const float* __restrict__ x, float* __restrict__ out)
{
    extern __shared__ char smem[];
    const uint32_t sb = smem_u32(smem);
    const int tid = threadIdx.x, wid = tid >> 5, lane = tid & 31;
    const int oct = blockIdx.x;          // 0..1 (oc half)
    const int rowbase = blockIdx.y * 2;  // 0..54 step 2
    const int nimg = blockIdx.z;

    const int wm = wid & 1;              // oc 64-half within CTA tile
    const int q  = wid >> 1;             // pixel quarter
    const int orow = q >> 1;             // 0..1
    const int c0 = (q & 1) * 32;         // col base

    const float* xb = x + (size_t)nimg * 256 * HWSQ;

    float acc[4][4][4];
    #pragma unroll
    for (int a = 0; a < 4; a++)
        #pragma unroll
        for (int b = 0; b < 4; b++)
            #pragma unroll
            for (int e = 0; e < 4; e++) acc[a][b][e] = 0.f;

    // issue A load for iter 0
    {
        const __half* src = g_wB + ((size_t)oct * 128) * 32;
        #pragma unroll
        for (int it = 0; it < 2; it++) {
            const int idx = tid + it * 256;          // 0..511
            const int r = idx >> 2, seg = idx & 3;
            const uint32_t dst = sb + SM_A + (uint32_t)(r * XROWB + seg * 16);
            asm volatile("cp.async.cg.shared.global [%0], [%1], 16;"
                         :: "r"(dst), "l"(src + r * 32 + seg * 8) : "memory");
        }
        asm volatile("cp.async.commit_group;" ::: "memory");
    }

    const int j = tid & 63;          // col index 0..63
    const int high = tid >> 6;       // 0..3

    for (int i = 0; i < 72; i++) {
        const int c = i / 9, t = i - c * 9;
        const int buf = i & 1;
        const int kh = t / 3, kw = t - kh * 3;

        if (t == 0) {
            // build x tile for chunk c: rows 0..3 (ih=rowbase-1+row),
            // cols 0..65 (iw=col-1), k 0..31 (ic = c*32+k)
            #pragma unroll 4
            for (int idx = high; idx < 128; idx += 4) {
                const int row = idx & 3, k = idx >> 2;
                const int ih = rowbase - 1 + row, iw = j - 1;
                float v = 0.f;
                if ((unsigned)ih < (unsigned)HW && (unsigned)iw < (unsigned)HW)
                    v = xb[(size_t)(c * 32 + k) * HWSQ + ih * HW + iw];
                const uint32_t off = (uint32_t)((row * 66 + j) * 40 + k) * 2;
                *(__half*)(smem + SM_XH + off) = __float2half_rn(v);
            }
            {   // tail cols 64,65
                const int k = tid & 31, row = (tid >> 5) & 3, col = 64 + (tid >> 7);
                const int ih = rowbase - 1 + row, iw = col - 1;
                float v = 0.f;
                if ((unsigned)ih < (unsigned)HW && (unsigned)iw < (unsigned)HW)
                    v = xb[(size_t)(c * 32 + k) * HWSQ + ih * HW + iw];
                const uint32_t off = (uint32_t)((row * 66 + col) * 40 + k) * 2;
                *(__half*)(smem + SM_XH + off) = __float2half_rn(v);
            }
        }

        asm volatile("cp.async.wait_group 0;" ::: "memory");
        __syncthreads();

        // prefetch next A
        if (i + 1 < 72) {
            const int c2 = (i + 1) / 9, t2 = (i + 1) - c2 * 9;
            const __half* src = g_wB + (((size_t)c2 * 9 + t2) * 256 + oct * 128) * 32;
            const uint32_t abase = sb + SM_A + (uint32_t)((buf ^ 1) * 10240);
            #pragma unroll
            for (int it = 0; it < 2; it++) {
                const int idx = tid + it * 256;
                const int r = idx >> 2, seg = idx & 3;
                asm volatile("cp.async.cg.shared.global [%0], [%1], 16;"
                             :: "r"(abase + (uint32_t)(r * XROWB + seg * 16)),
                                "l"(src + r * 32 + seg * 8) : "memory");
            }
            asm volatile("cp.async.commit_group;" ::: "memory");
        }

        // ---- compute this (chunk, tap) ----
        const uint32_t aB = sb + SM_A + (uint32_t)(buf * 10240)
                          + (uint32_t)((wm * 64 + (lane & 15)) * XROWB + ((lane >> 4) << 4));
        const int pxo = (lane & 7) + ((lane & 16) ? 8 : 0);
        const uint32_t kbo = (lane & 8) ? 16u : 0u;
        const uint32_t xoff = (uint32_t)(((orow + kh) * 66 + c0 + kw + pxo) * XROWB) + kbo;
        const uint32_t bH = sb + SM_XH + xoff;

        #pragma unroll
        for (int ks = 0; ks < 2; ks++) {
            const uint32_t ko = (uint32_t)(ks * 32);
            uint32_t bh[8];
            asm volatile("ldmatrix.sync.aligned.m8n8.x4.shared.b16 {%0,%1,%2,%3}, [%4];"
                : "=r"(bh[0]),"=r"(bh[1]),"=r"(bh[2]),"=r"(bh[3]) : "r"(bH + ko));
            asm volatile("ldmatrix.sync.aligned.m8n8.x4.shared.b16 {%0,%1,%2,%3}, [%4];"
                : "=r"(bh[4]),"=r"(bh[5]),"=r"(bh[6]),"=r"(bh[7]) : "r"(bH + ko + 16 * XROWB));
            #pragma unroll
            for (int mf = 0; mf < 4; mf++) {
                uint32_t a0, a1, a2, a3;
                asm volatile("ldmatrix.sync.aligned.m8n8.x4.shared.b16 {%0,%1,%2,%3}, [%4];"
                    : "=r"(a0),"=r"(a1),"=r"(a2),"=r"(a3)
                    : "r"(aB + (uint32_t)(mf * 16 * XROWB) + ko));
                #pragma unroll
                for (int nf = 0; nf < 4; nf++) {
                    asm volatile("mma.sync.aligned.m16n8k16.row.col.f32.f16.f16.f32 "
                        "{%0,%1,%2,%3}, {%4,%5,%6,%7}, {%8,%9}, {%0,%1,%2,%3};"
                        : "+f"(acc[mf][nf][0]),"+f"(acc[mf][nf][1]),
                          "+f"(acc[mf][nf][2]),"+f"(acc[mf][nf][3])
                        : "r"(a0),"r"(a1),"r"(a2),"r"(a3), "r"(bh[nf*2]),"r"(bh[nf*2+1]));
                }
            }
        }
        __syncthreads();
    }

    // ---- epilogue: scale by alpha, direct float2 stores ----
    const int oh = rowbase + orow;
    const int r = lane >> 2, cc = lane & 3;
    #pragma unroll
    for (int mf = 0; mf < 4; mf++) {
        const int oc = oct * 128 + wm * 64 + mf * 16 + r;
        const float al0 = g_alpha[oc];
        const float al1 = g_alpha[oc + 8];
        #pragma unroll
        for (int nf = 0; nf < 4; nf++) {
            const int ow = c0 + nf * 8 + cc * 2;
            if (ow < 56) {
                float* d0 = out + ((size_t)(nimg * 256 + oc)) * HWSQ + oh * HW + ow;
                float* d1 = d0 + (size_t)8 * HWSQ;
                *(float2*)d0 = make_float2(acc[mf][nf][0] * al0, acc[mf][nf][1] * al0);
                *(float2*)d1 = make_float2(acc[mf][nf][2] * al1, acc[mf][nf][3] * al1);
            }
        }
    }
}

extern "C" void kernel_launch(void* const* d_in, const int* in_sizes, int n_in,
                              void* d_out, int out_size) {
    const float* x = (const float*)d_in[0];
    const float* w = (const float*)d_in[1];
    float* out = (float*)d_out;

    quant_kernel<<<256, 256>>>(w);

    cudaFuncSetAttribute(conv_mma, cudaFuncAttributeMaxDynamicSharedMemorySize, SM_TOTAL);
    dim3 grid(2, 28, 32);
    conv_mma<<<grid, 256, SM_TOTAL>>>(x, out);

    (void)in_sizes; (void)n_in; (void)out_size;
}